// round 9
// baseline (speedup 1.0000x reference)
#include <cuda_runtime.h>
#include <math.h>

// reference(x) == softmax(max(x, axis=1), axis=-1)[:, None, :] * x
// (SSA groups=1 full-SVD reconstruction + diagonal averaging == identity on xm.)
//
// x: [B=256, H=64, N=2048] fp32. One block per batch row.
// Changes vs R2 measurement (60us kernel, DRAM 62%):
//  - float4 path: LDG.128/STG.128, halves LSU instructions and L1tex
//    wavefronts per byte (suspect SM-side pacing of DRAM).
//  - 512 threads, __launch_bounds__(512,4): 4 blocks/SM = 100% occupancy,
//    co-resident blocks drift out of phase -> fewer chip-wide DRAM lulls.
//  - online-softmax (m,s) pair reduction: one reduction tree, 2 barriers
//    instead of 4.

#define BATCH 256
#define HEADS 64
#define NCOLS 2048
#define NTHREADS 512            // each thread owns 4 columns
#define NV (NCOLS / 4)          // 512 float4 per head-row

__device__ __forceinline__ void combine(float& m, float& s, float mo, float so) {
    float M = fmaxf(m, mo);
    s = s * __expf(m - M) + so * __expf(mo - M);
    m = M;
}

__global__ __launch_bounds__(NTHREADS, 4)
void ssa_gate_kernel(const float* __restrict__ x, float* __restrict__ out) {
    const int b = blockIdx.x;
    const int t = threadIdx.x;

    const float4* __restrict__ xv =
        (const float4*)(x + (size_t)b * HEADS * NCOLS);
    float4* __restrict__ ov =
        (float4*)(out + (size_t)b * HEADS * NCOLS);

    __shared__ float sm[16];
    __shared__ float ss[16];
    __shared__ float sfin[2];

    // ---- phase 1: per-column max over heads (coalesced LDG.128) ----
    float4 cm = make_float4(-INFINITY, -INFINITY, -INFINITY, -INFINITY);
    #pragma unroll 8
    for (int h = 0; h < HEADS; h++) {
        float4 v = xv[h * NV + t];
        cm.x = fmaxf(cm.x, v.x);
        cm.y = fmaxf(cm.y, v.y);
        cm.z = fmaxf(cm.z, v.z);
        cm.w = fmaxf(cm.w, v.w);
    }

    // ---- thread-local online (m, s) over the 4 owned columns ----
    float m = fmaxf(fmaxf(cm.x, cm.y), fmaxf(cm.z, cm.w));
    float s = __expf(cm.x - m) + __expf(cm.y - m)
            + __expf(cm.z - m) + __expf(cm.w - m);

    // ---- warp butterfly on (m, s) ----
    #pragma unroll
    for (int o = 16; o > 0; o >>= 1) {
        float mo = __shfl_xor_sync(0xffffffffu, m, o);
        float so = __shfl_xor_sync(0xffffffffu, s, o);
        combine(m, s, mo, so);
    }
    if ((t & 31) == 0) { sm[t >> 5] = m; ss[t >> 5] = s; }
    __syncthreads();
    if (t < 32) {
        float mv = (t < 16) ? sm[t] : -INFINITY;
        float sv = (t < 16) ? ss[t] : 0.0f;
        #pragma unroll
        for (int o = 8; o > 0; o >>= 1) {
            float mo = __shfl_xor_sync(0xffffffffu, mv, o);
            float so = __shfl_xor_sync(0xffffffffu, sv, o);
            combine(mv, sv, mo, so);
        }
        if (t == 0) { sfin[0] = mv; sfin[1] = sv; }
    }
    __syncthreads();
    const float M   = sfin[0];
    const float inv = 1.0f / sfin[1];

    const float gx = __expf(cm.x - M) * inv;
    const float gy = __expf(cm.y - M) * inv;
    const float gz = __expf(cm.z - M) * inv;
    const float gw = __expf(cm.w - M) * inv;

    // ---- phase 2: scale + store (loads last-use -> evict-first; stores
    //      streaming -> never re-read) ----
    #pragma unroll 8
    for (int h = 0; h < HEADS; h++) {
        float4 v = __ldcs(&xv[h * NV + t]);
        v.x *= gx;
        v.y *= gy;
        v.z *= gz;
        v.w *= gw;
        __stcs(&ov[h * NV + t], v);
    }
}

extern "C" void kernel_launch(void* const* d_in, const int* in_sizes, int n_in,
                              void* d_out, int out_size) {
    const float* x = (const float*)d_in[0];
    float* out = (float*)d_out;
    ssa_gate_kernel<<<BATCH, NTHREADS>>>(x, out);
}